// round 2
// baseline (speedup 1.0000x reference)
#include <cuda_runtime.h>
#include <math.h>

// ---------------- problem constants ----------------
#define SLOTS      85      // 81 classes + 4 box coords
#define NBINS      4096
#define HIST_LO   (-8.0f)
#define HIST_INVW (256.0f)   // NBINS / (HI-LO) = 4096/16

// ---------------- device scratch (no allocations allowed) ----------------
__device__ int    g_npos;
__device__ double g_pos_loss;
__device__ double g_loc_loss;
__device__ int    g_hist_cnt[NBINS];
__device__ float  g_hist_sum[NBINS];

// ---------------- K0: zero scratch ----------------
__global__ void ssd_init_kernel() {
    int i = blockIdx.x * blockDim.x + threadIdx.x;
    if (i < NBINS) { g_hist_cnt[i] = 0; g_hist_sum[i] = 0.0f; }
    if (i == 0) { g_npos = 0; g_pos_loss = 0.0; g_loc_loss = 0.0; }
}

// ---------------- K1: streaming pass, 8 threads per anchor ----------------
// Each warp handles 4 consecutive anchors. Thread `sub` (0..7) of each 8-lane
// group covers slots sub, sub+8, ..., sub+80. The k=10 step holds slot 80+sub:
//   sub==0 -> class slot 80 (dot product), sub 1..4 -> box slots 81..84
//   (smooth-L1), sub 5..7 -> nothing.
__global__ __launch_bounds__(256) void ssd_main_kernel(
    const float* __restrict__ yp,
    const float* __restrict__ yt,
    int nanch)
{
    __shared__ int   s_cnt[NBINS];
    __shared__ float s_sum[NBINS];
    for (int i = threadIdx.x; i < NBINS; i += blockDim.x) { s_cnt[i] = 0; s_sum[i] = 0.0f; }
    __syncthreads();

    const int lane = threadIdx.x & 31;
    const int sub  = lane & 7;          // slot phase within anchor
    const int grp  = lane >> 3;         // which of the 4 anchors in this warp
    const int warp = threadIdx.x >> 5;

    long long wid     = (long long)blockIdx.x * (blockDim.x >> 5) + warp;
    long long nwarps  = (long long)gridDim.x * (blockDim.x >> 5);
    long long strideA = nwarps * 4;     // anchors consumed per grid iteration

    float accPos = 0.0f, accLoc = 0.0f;
    int   accN = 0;

    for (long long a0 = wid * 4; a0 < nanch; a0 += strideA) {
        long long a  = a0 + grp;
        bool      gv = (a < nanch);

        float c = 0.0f, sl = 0.0f, t00 = 0.0f;
        bool  pf = false;

        if (gv) {
            size_t row = (size_t)a * SLOTS + sub;

            // k = 0..9 : pure class slots (slot = sub + 8k <= 79... up to 72+sub)
            #pragma unroll
            for (int k = 0; k < 10; k++) {
                float t = yt[row + 8 * k];
                float p = yp[row + 8 * k];
                c = fmaf(t, p, c);
                if (k == 0) {
                    if (sub == 0) t00 = t;      // background slot value
                    else          pf |= (t != 0.0f);
                } else {
                    pf |= (t != 0.0f);
                }
            }
            // k = 10 : slot 80+sub
            if (sub <= 4) {
                float t = yt[row + 80];
                float p = yp[row + 80];
                if (sub == 0) {                  // class slot 80
                    c = fmaf(t, p, c);
                    pf |= (t != 0.0f);
                } else {                         // box slots 81..84
                    float d  = p - t;
                    float ad = fabsf(d);
                    sl = (ad < 1.0f) ? 0.5f * d * d : (ad - 0.5f);
                }
            }
        }

        // 8-lane segmented reduction (3 levels), both values in flight
        #pragma unroll
        for (int off = 4; off; off >>= 1) {
            c  += __shfl_down_sync(0xffffffffu, c,  off, 8);
            sl += __shfl_down_sync(0xffffffffu, sl, off, 8);
        }
        unsigned bal = __ballot_sync(0xffffffffu, pf);

        if (sub == 0 && gv) {
            bool  pos  = (bal >> (grp * 8)) & 0xffu;
            float conf = -c;
            if (pos) { accN++; accPos += conf; accLoc += sl; }
            if (t00 != 0.0f) {                   // negative (background) anchor
                int bin = (int)((conf - HIST_LO) * HIST_INVW);
                bin = max(0, min(NBINS - 1, bin));
                atomicAdd(&s_cnt[bin], 1);
                atomicAdd(&s_sum[bin], conf);
            }
        }
    }

    if (sub == 0 && accN) {
        atomicAdd(&g_npos, accN);
        atomicAdd(&g_pos_loss, (double)accPos);
        atomicAdd(&g_loc_loss, (double)accLoc);
    }

    __syncthreads();
    for (int i = threadIdx.x; i < NBINS; i += blockDim.x) {
        int cc = s_cnt[i];
        if (cc) {
            atomicAdd(&g_hist_cnt[i], cc);
            atomicAdd(&g_hist_sum[i], s_sum[i]);
        }
    }
}

// ---------------- K2: single-block finalize ----------------
__global__ __launch_bounds__(1024) void ssd_finalize_kernel(float* __restrict__ out)
{
    __shared__ int    s_cnt[NBINS];
    __shared__ float  s_sumf[NBINS];
    __shared__ int    s_chunk[1024];
    __shared__ double s_neg;

    const int tid = threadIdx.x;
    for (int i = tid; i < NBINS; i += 1024) {
        int b = NBINS - 1 - i;          // rank from the top value downward
        s_cnt[i]  = g_hist_cnt[b];
        s_sumf[i] = g_hist_sum[b];
    }
    if (tid == 0) s_neg = 0.0;
    __syncthreads();

    int c0 = s_cnt[tid * 4 + 0];
    int c1 = s_cnt[tid * 4 + 1];
    int c2 = s_cnt[tid * 4 + 2];
    int c3 = s_cnt[tid * 4 + 3];
    int total = c0 + c1 + c2 + c3;

    // inclusive Hillis-Steele scan of per-thread chunk totals
    s_chunk[tid] = total;
    __syncthreads();
    for (int off = 1; off < 1024; off <<= 1) {
        int v = (tid >= off) ? s_chunk[tid - off] : 0;
        __syncthreads();
        s_chunk[tid] += v;
        __syncthreads();
    }
    int cumBefore = s_chunk[tid] - total;   // negatives strictly above this chunk

    int npos = g_npos;
    int nneg = (int)(3.0f * (float)npos);

    double contrib = 0.0;
    int cb = cumBefore;
    int cnts[4] = {c0, c1, c2, c3};
    #pragma unroll
    for (int k = 0; k < 4; k++) {
        int cc = cnts[k];
        if (cc) {
            float s = s_sumf[tid * 4 + k];
            if (cb + cc <= nneg) {
                contrib += (double)s;                                    // fully taken
            } else if (cb < nneg) {
                contrib += (double)s * (double)(nneg - cb) / (double)cc; // straddling bin
            }
        }
        cb += cc;
    }
    if (contrib != 0.0) atomicAdd(&s_neg, contrib);
    __syncthreads();

    if (tid == 0) {
        double np = (npos > 0) ? (double)npos : 1.0;
        out[0] = (float)((g_pos_loss + s_neg + g_loc_loss) / np);
    }
}

// ---------------- entry point ----------------
extern "C" void kernel_launch(void* const* d_in, const int* in_sizes, int n_in,
                              void* d_out, int out_size)
{
    const float* y_pred = (const float*)d_in[0];
    const float* y_true = (const float*)d_in[1];
    float* out = (float*)d_out;

    int nanch = in_sizes[0] / SLOTS;

    ssd_init_kernel<<<(NBINS + 255) / 256, 256>>>();
    ssd_main_kernel<<<888, 256>>>(y_pred, y_true, nanch);
    ssd_finalize_kernel<<<1, 1024>>>(out);
}